// round 5
// baseline (speedup 1.0000x reference)
#include <cuda_runtime.h>

// FFM pairwise interactions:
//   inputs: (B=4096, 400, 64) fp32, v[b, j, i, e]
//   output: (B, 1, 190, 64) fp32, out[b,0,p,:] = v[b,jj,ii,:] * v[b,ii,jj,:]
// Pure HBM streaming, 597 MB floor. R5: Blackwell 256-bit ld/st.global.v8.f32
// with .cs streaming hints; one 32-B chunk per thread, warp = 1024 B contiguous.

constexpr int N_FIELDS = 20;
constexpr int NPAIRS   = 190;
constexpr int QUADS    = 16;                    // float4 per 64-elem row
constexpr int ROW_FLT  = N_FIELDS * N_FIELDS * 64;     // 25600 floats per batch
constexpr int TOTAL_F8 = 4096 * NPAIRS * 8;            // 6,220,800 32-B chunks
constexpr int THREADS  = 256;
constexpr int BLOCKS   = TOTAL_F8 / THREADS;           // 24300 exact

// Per-pair row offsets in floats: offA[p] = (j*20+i)*64, offC[p] = (i*20+j)*64
struct PairTab { int offA[NPAIRS]; int offC[NPAIRS]; };
constexpr PairTab make_tab() {
    PairTab t{};
    int p = 0;
    for (int i = 0; i < N_FIELDS; ++i)
        for (int j = i + 1; j < N_FIELDS; ++j, ++p) {
            t.offA[p] = (j * N_FIELDS + i) * 64;
            t.offC[p] = (i * N_FIELDS + j) * 64;
        }
    return t;
}
__constant__ PairTab TAB = make_tab();

__device__ __forceinline__ void ld256cs(const float* p, float* r) {
    asm volatile("ld.global.cs.v8.f32 {%0,%1,%2,%3,%4,%5,%6,%7}, [%8];"
        : "=f"(r[0]), "=f"(r[1]), "=f"(r[2]), "=f"(r[3]),
          "=f"(r[4]), "=f"(r[5]), "=f"(r[6]), "=f"(r[7])
        : "l"(p));
}

__device__ __forceinline__ void st256cs(float* p, const float* r) {
    asm volatile("st.global.cs.v8.f32 [%0], {%1,%2,%3,%4,%5,%6,%7,%8};"
        :: "l"(p),
           "f"(r[0]), "f"(r[1]), "f"(r[2]), "f"(r[3]),
           "f"(r[4]), "f"(r[5]), "f"(r[6]), "f"(r[7])
        : "memory");
}

__global__ void __launch_bounds__(THREADS)
ffm_pair_kernel(const float* __restrict__ in, float* __restrict__ out)
{
    int f8 = blockIdx.x * THREADS + threadIdx.x;   // 32-B chunk index, < 6.22M

    int q8 = f8 & 7;          // chunk within 256-B row (8 floats each)
    int bp = f8 >> 3;         // b * NPAIRS + p
    int p  = bp % NPAIRS;     // magic-mul
    int b  = bp / NPAIRS;

    const float* base = in + (long)b * ROW_FLT + q8 * 8;
    const float* pa = base + TAB.offA[p];   // v[b, j, i, q8*8 ..]
    const float* pc = base + TAB.offC[p];   // v[b, i, j, q8*8 ..]

    float a[8], c[8], r[8];
    ld256cs(pa, a);
    ld256cs(pc, c);

    #pragma unroll
    for (int k = 0; k < 8; ++k) r[k] = a[k] * c[k];

    st256cs(out + (long)f8 * 8, r);
}

extern "C" void kernel_launch(void* const* d_in, const int* in_sizes, int n_in,
                              void* d_out, int out_size)
{
    const float* in  = (const float*)d_in[0];
    float*       out = (float*)d_out;
    ffm_pair_kernel<<<BLOCKS, THREADS>>>(in, out);
}